// round 5
// baseline (speedup 1.0000x reference)
#include <cuda_runtime.h>
#include <math.h>

#define NN 5
#define BB 4
#define CC 256
#define SS 1024      // H*W
#define KDIM 256
#define CTILE 64
#define STILE 32
#define KCHUNK 16
#define NCHUNK (KDIM / KCHUNK)

// Precomputed transposed weights: [i][k][c]
__device__ float g_A[NN * KDIM * CC];    // W1 + W2
__device__ float g_W2[NN * KDIM * CC];   // W2

__global__ void prep_kernel(const float* __restrict__ conv_w) {
    int idx = blockIdx.x * blockDim.x + threadIdx.x;
    if (idx >= NN * KDIM * CC) return;
    int c = idx & (CC - 1);
    int k = (idx >> 8) & (KDIM - 1);
    int i = idx >> 16;
    // conv_w: [i][c][2C], W1 = [:, :, :C], W2 = [:, :, C:]
    float w1 = conv_w[((i * CC + c) << 9) + k];
    float w2 = conv_w[((i * CC + c) << 9) + CC + k];
    g_A[idx]  = w1 + w2;
    g_W2[idx] = w2;
}

// Packed f32x2 FMA (Blackwell dual-lane fp32 — 2x tput vs 3-reg FFMA)
#define FMA2(d, a, b, c) \
    asm("fma.rn.f32x2 %0, %1, %2, %3;" : "=l"(d) : "l"(a), "l"(b), "l"(c))
#define PACK2(d, v) \
    asm("mov.b64 %0, {%1, %2};" : "=l"(d) : "r"(__float_as_uint(v)), "r"(__float_as_uint(v)))

__device__ __forceinline__ float4 xload(const float* __restrict__ x, int b, int s0,
                                        int k0, int q) {
    int j  = q >> 7;          // 0..4  (128 float4 per node)
    int kk = (q >> 3) & 15;   // 0..15
    int s4 = q & 7;           // 0..7
    return *(const float4*)&x[((j * BB + b) * CC + k0 + kk) * SS + s0 + s4 * 4];
}
__device__ __forceinline__ int xsidx(int q) {
    int j  = q >> 7;
    int kk = (q >> 3) & 15;
    int s4 = q & 7;
    return (j * KCHUNK + kk) * STILE + s4 * 4;
}

__global__ __launch_bounds__(256, 2) void fused_kernel(
    const float* __restrict__ x, const float* __restrict__ w5,
    const float* __restrict__ conv_b, float* __restrict__ out) {
    __shared__ float sA[2][KCHUNK * CTILE];
    __shared__ float sW[2][KCHUNK * CTILE];
    __shared__ float sX[2][NN * KCHUNK * STILE];

    const int tid = threadIdx.x;
    const int i   = blockIdx.z;                 // output node
    const int c0  = blockIdx.y * CTILE;         // channel tile base
    const int b   = blockIdx.x >> 5;            // batch
    const int s0  = (blockIdx.x & 31) * STILE;  // spatial tile base

    const int cidx = tid >> 4;   // 0..15 -> c frag of 4
    const int sidx = tid & 15;   // 0..15 -> s frag of 2

    // global load mapping (A / W2): one float4 per thread per chunk
    const int lkA = tid >> 4;    // 0..15
    const int lcA = tid & 15;    // 0..15

    const float* gA = g_A  + i * KDIM * CC;
    const float* gW = g_W2 + i * KDIM * CC;

    const int q0 = tid, q1 = tid + 256, q2 = tid + 512;  // q2 valid if tid<128

    float4 rA, rW, rX0, rX1, rX2;

    // prologue: load chunk 0 into registers
    rA = *(const float4*)&gA[lkA * CC + c0 + lcA * 4];
    rW = *(const float4*)&gW[lkA * CC + c0 + lcA * 4];
    rX0 = xload(x, b, s0, 0, q0);
    rX1 = xload(x, b, s0, 0, q1);
    if (tid < 128) rX2 = xload(x, b, s0, 0, q2);

    unsigned long long accY[NN][4];
    unsigned long long accZ[4];
#pragma unroll
    for (int j = 0; j < NN; j++)
#pragma unroll
        for (int cf = 0; cf < 4; cf++) accY[j][cf] = 0ull;
#pragma unroll
    for (int cf = 0; cf < 4; cf++) accZ[cf] = 0ull;

    int buf = 0;
#pragma unroll 1
    for (int kc = 0; kc < NCHUNK; kc++) {
        // stage registers -> smem
        *(float4*)&sA[buf][lkA * CTILE + lcA * 4] = rA;
        *(float4*)&sW[buf][lkA * CTILE + lcA * 4] = rW;
        *(float4*)&sX[buf][xsidx(q0)] = rX0;
        *(float4*)&sX[buf][xsidx(q1)] = rX1;
        if (tid < 128) *(float4*)&sX[buf][xsidx(q2)] = rX2;
        __syncthreads();

        // prefetch next chunk into registers (overlaps with compute)
        if (kc + 1 < NCHUNK) {
            int k0 = (kc + 1) * KCHUNK;
            rA = *(const float4*)&gA[(k0 + lkA) * CC + c0 + lcA * 4];
            rW = *(const float4*)&gW[(k0 + lkA) * CC + c0 + lcA * 4];
            rX0 = xload(x, b, s0, k0, q0);
            rX1 = xload(x, b, s0, k0, q1);
            if (tid < 128) rX2 = xload(x, b, s0, k0, q2);
        }

        const float* cA = sA[buf];
        const float* cW = sW[buf];
        const float* cX = sX[buf];
#pragma unroll
        for (int kk = 0; kk < KCHUNK; kk++) {
            float4 a  = *(const float4*)&cA[kk * CTILE + cidx * 4];
            float4 wv = *(const float4*)&cW[kk * CTILE + cidx * 4];
            unsigned long long xv[NN], xvi;
#pragma unroll
            for (int j = 0; j < NN; j++)
                xv[j] = *(const unsigned long long*)&cX[(j * KCHUNK + kk) * STILE + sidx * 2];
            xvi = *(const unsigned long long*)&cX[(i * KCHUNK + kk) * STILE + sidx * 2];
#pragma unroll
            for (int cf = 0; cf < 4; cf++) {
                float av  = (cf == 0) ? a.x  : (cf == 1) ? a.y  : (cf == 2) ? a.z  : a.w;
                float wvv = (cf == 0) ? wv.x : (cf == 1) ? wv.y : (cf == 2) ? wv.z : wv.w;
                unsigned long long aa, ww;
                PACK2(aa, av);
                PACK2(ww, wvv);
#pragma unroll
                for (int j = 0; j < NN; j++) FMA2(accY[j][cf], aa, xv[j], accY[j][cf]);
                FMA2(accZ[cf], ww, xvi, accZ[cf]);
            }
        }
        __syncthreads();
        buf ^= 1;
    }

    // ---- epilogue: distance -> sigmoid*w -> threshold -> norm over j -> out ----
    float wrow[NN];
#pragma unroll
    for (int j = 0; j < NN; j++) wrow[j] = w5[i * NN + j];

#pragma unroll
    for (int cf = 0; cf < 4; cf++) {
        int c = c0 + cidx * 4 + cf;
        float bic = conv_b[i * CC + c];
        float2 zz = *(float2*)&accZ[cf];
#pragma unroll
        for (int sf = 0; sf < 2; sf++) {
            int s = s0 + sidx * 2 + sf;
            float z = sf ? zz.y : zz.x;
            float num = 0.0f, n2 = 0.0f;
#pragma unroll
            for (int j = 0; j < NN; j++) {
                float xvv = x[((j * BB + b) * CC + c) * SS + s];
                float2 yy = *(float2*)&accY[j][cf];
                float y = sf ? yy.y : yy.x;
                float d = xvv - (y + z + bic);
                float t = d * wrow[j];
                float e = 1.0f / (1.0f + expf(-t));
                e = (e > 0.3f) ? e : 0.0f;
                n2  = fmaf(e, e, n2);
                num = fmaf(e, xvv, num);
            }
            out[((i * BB + b) * CC + c) * SS + s] = num / fmaxf(sqrtf(n2), 1e-12f);
        }
    }
}

extern "C" void kernel_launch(void* const* d_in, const int* in_sizes, int n_in,
                              void* d_out, int out_size) {
    // Identify inputs by element count (all distinct):
    // x: 5*4*256*32*32 = 5242880, w: 25, conv_w: 5*256*512 = 655360, conv_b: 5*256 = 1280
    const float* x = nullptr;
    const float* w = nullptr;
    const float* conv_w = nullptr;
    const float* conv_b = nullptr;
    for (int t = 0; t < n_in; t++) {
        switch (in_sizes[t]) {
            case 5242880: x = (const float*)d_in[t]; break;
            case 25:      w = (const float*)d_in[t]; break;
            case 655360:  conv_w = (const float*)d_in[t]; break;
            case 1280:    conv_b = (const float*)d_in[t]; break;
            default: break;
        }
    }
    float* out = (float*)d_out;

    prep_kernel<<<(NN * KDIM * CC + 255) / 256, 256>>>(conv_w);

    dim3 grid(BB * 32, CC / CTILE, NN);  // (b,s-tile) x c-tile x i
    fused_kernel<<<grid, 256>>>(x, w, conv_b, out);
}